// round 10
// baseline (speedup 1.0000x reference)
#include <cuda_runtime.h>

#define TPB 256
#define NLAYER 4
#define LN_EPS 1e-5f

typedef unsigned long long u64;

// Packed fp32-pair ops (Blackwell f32x2 pipe; ptxas never auto-fuses these).
__device__ __forceinline__ void fma2(u64& acc, u64 a, u64 w) {
    asm("fma.rn.f32x2 %0, %1, %2, %0;" : "+l"(acc) : "l"(a), "l"(w));
}
__device__ __forceinline__ u64 pack2(float v) {
    u64 r; asm("mov.b64 %0, {%1, %1};" : "=l"(r) : "f"(v)); return r;
}
__device__ __forceinline__ void mul2(u64& a, u64 b) {
    asm("mul.rn.f32x2 %0, %0, %1;" : "+l"(a) : "l"(b));
}
__device__ __forceinline__ void add2(u64& a, u64 b) {
    asm("add.rn.f32x2 %0, %0, %1;" : "+l"(a) : "l"(b));
}

// ~99 KB shared -> 2 blocks/SM. All hot arrays stride-36 rows (16B aligned).
struct __align__(16) Smem {
    float R[NLAYER][32][32];        // conv_root
    float W[NLAYER][3][32][32];     // conv_w
    float bias[NLAYER][32];
    float Wf[6][32];
    float bf[32], lng[32], lnb[32];
    float xs[64][36];               // node features
    float Lij[16][36];              // line sums over k, rows (i*4+j)
    float Lik[16][36];              // line sums over j, rows (i*4+k)
    float Si[4][36];                // plane sums over (j,k)
    float Sj[4][36];                // plane sums over (i,k)
    float Sk[4][36];                // plane sums over (i,j)
    float AW[3][16][36];            // agg_r @ W_r
    float Hroot[64][36];            // x @ R + bias
    float zero[36];                 // guard operand for inactive threads
};

// minBlocksPerMultiprocessor=2 raises the ptxas register ceiling to 128
// (was defaulting to 64, which blocked load hoisting in the unrolled
// Phase B and exposed a ~29cy LDS scoreboard stall per 4-k chunk).
// Residency is unchanged: 99KB smem already caps us at 2 blocks/SM.
__global__ __launch_bounds__(TPB, 2) void gnn_frame0_kernel(
    const float* __restrict__ xx, const float* __restrict__ ss,
    const float* __restrict__ W_f, const float* __restrict__ b_f,
    const float* __restrict__ conv_w, const float* __restrict__ conv_root,
    const float* __restrict__ conv_bias, const float* __restrict__ ln_g,
    const float* __restrict__ ln_b, float* __restrict__ out)
{
    extern __shared__ __align__(16) unsigned char smem_raw[];
    Smem* s = reinterpret_cast<Smem*>(smem_raw);
    const int tid = threadIdx.x;
    const int b = blockIdx.x;

    // ---- stage weights (float4, coalesced) ----
    {
        float4*       dRW = reinterpret_cast<float4*>(&s->R[0][0][0]);
        const float4* gR  = reinterpret_cast<const float4*>(conv_root);
        const float4* gW  = reinterpret_cast<const float4*>(conv_w);
        #pragma unroll
        for (int i = tid; i < 4096; i += TPB)
            dRW[i] = (i < 1024) ? gR[i] : gW[i - 1024];
        if (tid < 32) {
            reinterpret_cast<float4*>(&s->bias[0][0])[tid] =
                reinterpret_cast<const float4*>(conv_bias)[tid];
        } else if (tid < 80) {
            reinterpret_cast<float4*>(&s->Wf[0][0])[tid - 32] =
                reinterpret_cast<const float4*>(W_f)[tid - 32];
        } else if (tid < 112) {
            s->bf[tid - 80] = b_f[tid - 80];
        } else if (tid < 144) {
            s->lng[tid - 112] = ln_g[tid - 112];
        } else if (tid < 176) {
            s->lnb[tid - 144] = ln_b[tid - 144];
        } else if (tid < 212) {
            s->zero[tid - 176] = 0.0f;
        }
    }

    // thread -> (node, 8-channel group) for init / combine phases
    const int nd  = tid >> 2;
    const int ch0 = (tid & 3) * 8;
    const int ii = nd >> 4, jj = (nd >> 2) & 3, kk = nd & 3;
    const int rij = (ii << 2) | jj;
    const int rik = (ii << 2) | kk;

    __syncthreads();

    // ---- initial features (frame t=0): x0 = feats @ W_f + b_f ----
    {
        const float fi = ii * (1.0f / 3.0f);
        const float fj = jj * (1.0f / 3.0f);
        const float fk = kk * (1.0f / 3.0f);
        const float v  = xx[b * 512 + nd];   // frame 0 = first 64 nodes
        const float m  = ss[b] * 0.125f;     // ss / T
        #pragma unroll
        for (int q = 0; q < 8; q++) {
            int c = ch0 + q;
            s->xs[nd][c] = s->bf[c] + fi * s->Wf[0][c] + fj * s->Wf[1][c]
                         + fk * s->Wf[2][c] + v * s->Wf[4][c] + m * s->Wf[5][c];
        }
    }
    __syncthreads();

    // ---- Phase-B mapping: 56 row-pairs x 4 eighth-slices = 224 threads ----
    // pairs 0..23  -> AW (warps 0..2, one relation each; pair shares plane)
    // pairs 24..55 -> root (warps 3..6)
    const int pairIdx = tid >> 2;
    const int cc8 = (tid & 3) * 8;
    const float* aP  = s->zero;
    const float* aL0 = s->zero;
    const float* aL1 = s->zero;
    float* dst0 = s->zero;             // inactive threads never store
    float* dst1 = s->zero;
    int  wOff = 0;
    bool isRoot = false;
    if (tid < 224) {
        if (pairIdx < 24) {
            int r = pairIdx >> 3, t = pairIdx & 7;
            int rowA, rowB;
            wOff = r * 1024;
            if (r == 0) {            // rows i*4+j; pair same i (shares Si)
                rowA = 2 * t; rowB = 2 * t + 1;
                aP = s->Si[t >> 1]; aL0 = s->Lij[rowA]; aL1 = s->Lij[rowB];
            } else if (r == 1) {     // pair same j, i and i+1 (shares Sj)
                int j = t & 3, i0 = (t >> 2) * 2;
                rowA = i0 * 4 + j; rowB = (i0 + 1) * 4 + j;
                aP = s->Sj[j]; aL0 = s->Lij[rowA]; aL1 = s->Lij[rowB];
            } else {                 // pair same k, i and i+1 (shares Sk)
                int k = t & 3, i0 = (t >> 2) * 2;
                rowA = i0 * 4 + k; rowB = (i0 + 1) * 4 + k;
                aP = s->Sk[k]; aL0 = s->Lik[rowA]; aL1 = s->Lik[rowB];
            }
            dst0 = &s->AW[r][rowA][cc8];
            dst1 = &s->AW[r][rowB][cc8];
        } else {
            int n0 = (pairIdx - 24) * 2;
            aL0 = s->xs[n0]; aL1 = s->xs[n0 + 1];
            dst0 = &s->Hroot[n0][cc8];
            dst1 = &s->Hroot[n0 + 1][cc8];
            isRoot = true;
        }
    }

    // ---- 4 R-GCN layers ----
    for (int l = 0; l < NLAYER; l++) {
        // Phase A: line sums (512 items) + plane sums (384 items), one sync.
        #pragma unroll
        for (int v = tid; v < 512; v += TPB) {
            int rr = v >> 5, c = v & 31;
            s->Lij[rr][c] = s->xs[rr * 4 + 0][c] + s->xs[rr * 4 + 1][c]
                          + s->xs[rr * 4 + 2][c] + s->xs[rr * 4 + 3][c];
            int base = (rr >> 2) * 16 + (rr & 3);
            s->Lik[rr][c] = s->xs[base][c] + s->xs[base + 4][c]
                          + s->xs[base + 8][c] + s->xs[base + 12][c];
        }
        #pragma unroll
        for (int t = tid; t < 384; t += TPB) {
            int which = t >> 7, idx = (t >> 5) & 3, c = t & 31;
            float acc = 0.0f;
            if (which == 0) {
                #pragma unroll
                for (int m = 0; m < 16; m++) acc += s->xs[idx * 16 + m][c];
                s->Si[idx][c] = acc;
            } else if (which == 1) {
                #pragma unroll
                for (int i2 = 0; i2 < 4; i2++)
                    #pragma unroll
                    for (int k2 = 0; k2 < 4; k2++)
                        acc += s->xs[i2 * 16 + idx * 4 + k2][c];
                s->Sj[idx][c] = acc;
            } else {
                #pragma unroll
                for (int i2 = 0; i2 < 4; i2++)
                    #pragma unroll
                    for (int j2 = 0; j2 < 4; j2++)
                        acc += s->xs[i2 * 16 + j2 * 4 + idx][c];
                s->Sk[idx][c] = acc;
            }
        }
        __syncthreads();

        // Phase B: 2 rows x 8 channels per thread; weights loaded once per pair.
        if (tid < 224) {
            u64 acc0[4] = {0, 0, 0, 0}, acc1[4] = {0, 0, 0, 0};
            if (!isRoot) {
                const float* Wl = &s->W[l][0][0][0] + wOff;
                #pragma unroll
                for (int k0 = 0; k0 < 32; k0 += 4) {
                    float4 p4  = *reinterpret_cast<const float4*>(aP  + k0);
                    float4 l04 = *reinterpret_cast<const float4*>(aL0 + k0);
                    float4 l14 = *reinterpret_cast<const float4*>(aL1 + k0);
                    #pragma unroll
                    for (int kq = 0; kq < 4; kq++) {
                        float pv = (&p4.x)[kq];
                        u64 a0 = pack2(pv - (&l04.x)[kq]);
                        u64 a1 = pack2(pv - (&l14.x)[kq]);
                        const ulonglong2* w2 =
                            reinterpret_cast<const ulonglong2*>(Wl + (k0 + kq) * 32 + cc8);
                        ulonglong2 wA = w2[0], wB = w2[1];
                        fma2(acc0[0], a0, wA.x); fma2(acc0[1], a0, wA.y);
                        fma2(acc0[2], a0, wB.x); fma2(acc0[3], a0, wB.y);
                        fma2(acc1[0], a1, wA.x); fma2(acc1[1], a1, wA.y);
                        fma2(acc1[2], a1, wB.x); fma2(acc1[3], a1, wB.y);
                    }
                }
                u64 s2 = pack2(1.0f / 12.0f);
                #pragma unroll
                for (int q = 0; q < 4; q++) { mul2(acc0[q], s2); mul2(acc1[q], s2); }
            } else {
                const float* Wl = &s->R[l][0][0];
                #pragma unroll
                for (int k0 = 0; k0 < 32; k0 += 4) {
                    float4 l04 = *reinterpret_cast<const float4*>(aL0 + k0);
                    float4 l14 = *reinterpret_cast<const float4*>(aL1 + k0);
                    #pragma unroll
                    for (int kq = 0; kq < 4; kq++) {
                        u64 a0 = pack2((&l04.x)[kq]);
                        u64 a1 = pack2((&l14.x)[kq]);
                        const ulonglong2* w2 =
                            reinterpret_cast<const ulonglong2*>(Wl + (k0 + kq) * 32 + cc8);
                        ulonglong2 wA = w2[0], wB = w2[1];
                        fma2(acc0[0], a0, wA.x); fma2(acc0[1], a0, wA.y);
                        fma2(acc0[2], a0, wB.x); fma2(acc0[3], a0, wB.y);
                        fma2(acc1[0], a1, wA.x); fma2(acc1[1], a1, wA.y);
                        fma2(acc1[2], a1, wB.x); fma2(acc1[3], a1, wB.y);
                    }
                }
                const ulonglong2* bb =
                    reinterpret_cast<const ulonglong2*>(&s->bias[l][cc8]);
                ulonglong2 b0 = bb[0], b1 = bb[1];
                add2(acc0[0], b0.x); add2(acc0[1], b0.y);
                add2(acc0[2], b1.x); add2(acc0[3], b1.y);
                add2(acc1[0], b0.x); add2(acc1[1], b0.y);
                add2(acc1[2], b1.x); add2(acc1[3], b1.y);
            }
            ulonglong2* d0 = reinterpret_cast<ulonglong2*>(dst0);
            d0[0] = make_ulonglong2(acc0[0], acc0[1]);
            d0[1] = make_ulonglong2(acc0[2], acc0[3]);
            ulonglong2* d1 = reinterpret_cast<ulonglong2*>(dst1);
            d1[0] = make_ulonglong2(acc1[0], acc1[1]);
            d1[1] = make_ulonglong2(acc1[2], acc1[3]);
        }
        __syncthreads();

        // Phase C: combine + ReLU + LayerNorm (64 nodes x 4 groups of 8 ch).
        {
            float h[8];
            const float4* a0 = reinterpret_cast<const float4*>(&s->AW[0][rij][ch0]);
            const float4* a1 = reinterpret_cast<const float4*>(&s->AW[1][rij][ch0]);
            const float4* a2 = reinterpret_cast<const float4*>(&s->AW[2][rik][ch0]);
            const float4* hr = reinterpret_cast<const float4*>(&s->Hroot[nd][ch0]);
            #pragma unroll
            for (int q4 = 0; q4 < 2; q4++) {
                float4 v0 = a0[q4], v1 = a1[q4], v2 = a2[q4], vr = hr[q4];
                h[q4 * 4 + 0] = v0.x + v1.x + v2.x + vr.x;
                h[q4 * 4 + 1] = v0.y + v1.y + v2.y + vr.y;
                h[q4 * 4 + 2] = v0.z + v1.z + v2.z + vr.z;
                h[q4 * 4 + 3] = v0.w + v1.w + v2.w + vr.w;
            }
            float ssum = 0.0f, sq = 0.0f;
            #pragma unroll
            for (int q = 0; q < 8; q++) {
                h[q] = fmaxf(h[q], 0.0f);
                ssum += h[q];
                sq   += h[q] * h[q];
            }
            ssum += __shfl_xor_sync(0xffffffffu, ssum, 1);
            sq   += __shfl_xor_sync(0xffffffffu, sq, 1);
            ssum += __shfl_xor_sync(0xffffffffu, ssum, 2);
            sq   += __shfl_xor_sync(0xffffffffu, sq, 2);
            float mu  = ssum * (1.0f / 32.0f);
            float var = sq * (1.0f / 32.0f) - mu * mu;
            float rs  = rsqrtf(var + LN_EPS);
            #pragma unroll
            for (int q = 0; q < 8; q++) {
                int c = ch0 + q;
                s->xs[nd][c] = (h[q] - mu) * rs * s->lng[c] + s->lnb[c];
            }
        }
        __syncthreads();
    }

    // ---- output: three axis-means over the 4x4x4 frame -> (48, 32) ----
    float* outb = out + (size_t)b * 48 * 32;
    #pragma unroll
    for (int v = tid; v < 1536; v += TPB) {
        int o = v >> 5, c = v & 31;
        float val;
        if (o < 16) {               // mean over i; o = j*4+k
            val = s->xs[o][c] + s->xs[o + 16][c] + s->xs[o + 32][c] + s->xs[o + 48][c];
        } else if (o < 32) {        // mean over j; (o-16) = i*4+k
            int oo = o - 16; int base = (oo >> 2) * 16 + (oo & 3);
            val = s->xs[base][c] + s->xs[base + 4][c] + s->xs[base + 8][c] + s->xs[base + 12][c];
        } else {                    // mean over k; (o-32) = i*4+j
            int oo = o - 32; int base = (oo >> 2) * 16 + (oo & 3) * 4;
            val = s->xs[base][c] + s->xs[base + 1][c] + s->xs[base + 2][c] + s->xs[base + 3][c];
        }
        outb[o * 32 + c] = val * 0.25f;
    }
}

extern "C" void kernel_launch(void* const* d_in, const int* in_sizes, int n_in,
                              void* d_out, int out_size) {
    const float* xx        = (const float*)d_in[0];
    const float* ss        = (const float*)d_in[1];
    const float* W_f       = (const float*)d_in[2];
    const float* b_f       = (const float*)d_in[3];
    const float* conv_w    = (const float*)d_in[4];
    const float* conv_root = (const float*)d_in[5];
    const float* conv_bias = (const float*)d_in[6];
    const float* ln_g      = (const float*)d_in[7];
    const float* ln_b      = (const float*)d_in[8];
    // d_in[9]/d_in[10] (src/dst) unused: aggregation has a closed form.

    const int B = in_sizes[1];

    cudaFuncSetAttribute(gnn_frame0_kernel,
                         cudaFuncAttributeMaxDynamicSharedMemorySize,
                         (int)sizeof(Smem));
    gnn_frame0_kernel<<<B, TPB, sizeof(Smem)>>>(
        xx, ss, W_f, b_f, conv_w, conv_root, conv_bias, ln_g, ln_b,
        (float*)d_out);
}

// round 11
// speedup vs baseline: 1.0285x; 1.0285x over previous
#include <cuda_runtime.h>

#define TPB 256
#define NLAYER 4
#define LN_EPS 1e-5f

typedef unsigned long long u64;

// Packed fp32-pair ops (Blackwell f32x2 pipe; ptxas never auto-fuses these).
__device__ __forceinline__ void fma2(u64& acc, u64 a, u64 w) {
    asm("fma.rn.f32x2 %0, %1, %2, %0;" : "+l"(acc) : "l"(a), "l"(w));
}
__device__ __forceinline__ u64 pack2(float v) {
    u64 r; asm("mov.b64 %0, {%1, %1};" : "=l"(r) : "f"(v)); return r;
}
__device__ __forceinline__ void mul2(u64& a, u64 b) {
    asm("mul.rn.f32x2 %0, %0, %1;" : "+l"(a) : "l"(b));
}
__device__ __forceinline__ void add2(u64& a, u64 b) {
    asm("add.rn.f32x2 %0, %0, %1;" : "+l"(a) : "l"(b));
}

// ~99 KB shared -> 2 blocks/SM. All hot arrays stride-36 rows (16B aligned).
struct __align__(16) Smem {
    float R[NLAYER][32][32];        // conv_root
    float W[NLAYER][3][32][32];     // conv_w
    float bias[NLAYER][32];
    float Wf[6][32];
    float bf[32], lng[32], lnb[32];
    float xs[64][36];               // node features
    float Lij[16][36];              // line sums over k, rows (i*4+j)
    float Lik[16][36];              // line sums over j, rows (i*4+k)
    float Si[4][36];                // plane sums over (j,k)
    float Sj[4][36];                // plane sums over (i,k)
    float Sk[4][36];                // plane sums over (i,j)
    float AW[3][16][36];            // agg_r @ W_r
    float Hroot[64][36];            // x @ R + bias
    float zero[36];                 // guard operand for inactive threads
};

__global__ __launch_bounds__(TPB) void gnn_frame0_kernel(
    const float* __restrict__ xx, const float* __restrict__ ss,
    const float* __restrict__ W_f, const float* __restrict__ b_f,
    const float* __restrict__ conv_w, const float* __restrict__ conv_root,
    const float* __restrict__ conv_bias, const float* __restrict__ ln_g,
    const float* __restrict__ ln_b, float* __restrict__ out)
{
    extern __shared__ __align__(16) unsigned char smem_raw[];
    Smem* s = reinterpret_cast<Smem*>(smem_raw);
    const int tid = threadIdx.x;
    const int b = blockIdx.x;

    // ---- stage weights (float4, coalesced) ----
    {
        float4*       dRW = reinterpret_cast<float4*>(&s->R[0][0][0]);
        const float4* gR  = reinterpret_cast<const float4*>(conv_root);
        const float4* gW  = reinterpret_cast<const float4*>(conv_w);
        #pragma unroll
        for (int i = tid; i < 4096; i += TPB)
            dRW[i] = (i < 1024) ? gR[i] : gW[i - 1024];
        if (tid < 32) {
            reinterpret_cast<float4*>(&s->bias[0][0])[tid] =
                reinterpret_cast<const float4*>(conv_bias)[tid];
        } else if (tid < 80) {
            reinterpret_cast<float4*>(&s->Wf[0][0])[tid - 32] =
                reinterpret_cast<const float4*>(W_f)[tid - 32];
        } else if (tid < 112) {
            s->bf[tid - 80] = b_f[tid - 80];
        } else if (tid < 144) {
            s->lng[tid - 112] = ln_g[tid - 112];
        } else if (tid < 176) {
            s->lnb[tid - 144] = ln_b[tid - 144];
        } else if (tid < 212) {
            s->zero[tid - 176] = 0.0f;
        }
    }

    // thread -> (node, 8-channel group) for init / combine phases
    const int nd  = tid >> 2;
    const int ch0 = (tid & 3) * 8;
    const int ii = nd >> 4, jj = (nd >> 2) & 3, kk = nd & 3;
    const int rij = (ii << 2) | jj;
    const int rik = (ii << 2) | kk;

    __syncthreads();

    // ---- initial features (frame t=0): x0 = feats @ W_f + b_f ----
    {
        const float fi = ii * (1.0f / 3.0f);
        const float fj = jj * (1.0f / 3.0f);
        const float fk = kk * (1.0f / 3.0f);
        const float v  = xx[b * 512 + nd];   // frame 0 = first 64 nodes
        const float m  = ss[b] * 0.125f;     // ss / T
        #pragma unroll
        for (int q = 0; q < 8; q++) {
            int c = ch0 + q;
            s->xs[nd][c] = s->bf[c] + fi * s->Wf[0][c] + fj * s->Wf[1][c]
                         + fk * s->Wf[2][c] + v * s->Wf[4][c] + m * s->Wf[5][c];
        }
    }
    __syncthreads();

    // ---- Phase-B mapping: 56 row-pairs x 4 eighth-slices = 224 threads ----
    // pairs 0..23  -> AW (warps 0..2; exactly tid<96)
    // pairs 24..55 -> root (warps 3..6; exactly 96<=tid<224)
    const int pairIdx = tid >> 2;
    const int cc8 = (tid & 3) * 8;
    const float* aP  = s->zero;
    const float* aL0 = s->zero;
    const float* aL1 = s->zero;
    float* dst0 = s->zero;             // warp-7 threads never store
    float* dst1 = s->zero;
    int  wOff = 0;
    if (tid < 224) {
        if (pairIdx < 24) {
            int r = pairIdx >> 3, t = pairIdx & 7;
            int rowA, rowB;
            wOff = r * 1024;
            if (r == 0) {            // rows i*4+j; pair same i (shares Si)
                rowA = 2 * t; rowB = 2 * t + 1;
                aP = s->Si[t >> 1]; aL0 = s->Lij[rowA]; aL1 = s->Lij[rowB];
            } else if (r == 1) {     // pair same j, i and i+1 (shares Sj)
                int j = t & 3, i0 = (t >> 2) * 2;
                rowA = i0 * 4 + j; rowB = (i0 + 1) * 4 + j;
                aP = s->Sj[j]; aL0 = s->Lij[rowA]; aL1 = s->Lij[rowB];
            } else {                 // pair same k, i and i+1 (shares Sk)
                int k = t & 3, i0 = (t >> 2) * 2;
                rowA = i0 * 4 + k; rowB = (i0 + 1) * 4 + k;
                aP = s->Sk[k]; aL0 = s->Lik[rowA]; aL1 = s->Lik[rowB];
            }
            dst0 = &s->AW[r][rowA][cc8];
            dst1 = &s->AW[r][rowB][cc8];
        } else {
            int n0 = (pairIdx - 24) * 2;
            aL0 = s->xs[n0]; aL1 = s->xs[n0 + 1];
            dst0 = &s->Hroot[n0][cc8];
            dst1 = &s->Hroot[n0 + 1][cc8];
        }
    }

    // ---- 4 R-GCN layers: warp-specialized (sums+AW) || root overlap ----
    for (int l = 0; l < NLAYER; l++) {
        if (tid < 96 || tid >= 224) {
            // === sums group: warps 0-2 + warp 7 (128 threads) ===
            const int idx = (tid < 96) ? tid : (tid - 128);   // 0..127
            // line sums: 512 items / 128 threads = 4 iters
            #pragma unroll
            for (int v = idx; v < 512; v += 128) {
                int rr = v >> 5, c = v & 31;
                s->Lij[rr][c] = s->xs[rr * 4 + 0][c] + s->xs[rr * 4 + 1][c]
                              + s->xs[rr * 4 + 2][c] + s->xs[rr * 4 + 3][c];
                int base = (rr >> 2) * 16 + (rr & 3);
                s->Lik[rr][c] = s->xs[base][c] + s->xs[base + 4][c]
                              + s->xs[base + 8][c] + s->xs[base + 12][c];
            }
            // plane sums: 384 items / 128 threads = 3 iters
            #pragma unroll
            for (int t = idx; t < 384; t += 128) {
                int which = t >> 7, idx4 = (t >> 5) & 3, c = t & 31;
                float acc = 0.0f;
                if (which == 0) {
                    #pragma unroll
                    for (int m = 0; m < 16; m++) acc += s->xs[idx4 * 16 + m][c];
                    s->Si[idx4][c] = acc;
                } else if (which == 1) {
                    #pragma unroll
                    for (int i2 = 0; i2 < 4; i2++)
                        #pragma unroll
                        for (int k2 = 0; k2 < 4; k2++)
                            acc += s->xs[i2 * 16 + idx4 * 4 + k2][c];
                    s->Sj[idx4][c] = acc;
                } else {
                    #pragma unroll
                    for (int i2 = 0; i2 < 4; i2++)
                        #pragma unroll
                        for (int j2 = 0; j2 < 4; j2++)
                            acc += s->xs[i2 * 16 + j2 * 4 + idx4][c];
                    s->Sk[idx4][c] = acc;
                }
            }
            // named barrier among the 128 sums threads only
            asm volatile("bar.sync 1, 128;" ::: "memory");

            if (tid < 96) {
                // === AW matmul (24 pairs x 4 slices) ===
                u64 acc0[4] = {0, 0, 0, 0}, acc1[4] = {0, 0, 0, 0};
                const float* Wl = &s->W[l][0][0][0] + wOff;
                #pragma unroll
                for (int k0 = 0; k0 < 32; k0 += 4) {
                    float4 p4  = *reinterpret_cast<const float4*>(aP  + k0);
                    float4 l04 = *reinterpret_cast<const float4*>(aL0 + k0);
                    float4 l14 = *reinterpret_cast<const float4*>(aL1 + k0);
                    #pragma unroll
                    for (int kq = 0; kq < 4; kq++) {
                        float pv = (&p4.x)[kq];
                        u64 a0 = pack2(pv - (&l04.x)[kq]);
                        u64 a1 = pack2(pv - (&l14.x)[kq]);
                        const ulonglong2* w2 =
                            reinterpret_cast<const ulonglong2*>(Wl + (k0 + kq) * 32 + cc8);
                        ulonglong2 wA = w2[0], wB = w2[1];
                        fma2(acc0[0], a0, wA.x); fma2(acc0[1], a0, wA.y);
                        fma2(acc0[2], a0, wB.x); fma2(acc0[3], a0, wB.y);
                        fma2(acc1[0], a1, wA.x); fma2(acc1[1], a1, wA.y);
                        fma2(acc1[2], a1, wB.x); fma2(acc1[3], a1, wB.y);
                    }
                }
                u64 s2 = pack2(1.0f / 12.0f);
                #pragma unroll
                for (int q = 0; q < 4; q++) { mul2(acc0[q], s2); mul2(acc1[q], s2); }
                ulonglong2* d0 = reinterpret_cast<ulonglong2*>(dst0);
                d0[0] = make_ulonglong2(acc0[0], acc0[1]);
                d0[1] = make_ulonglong2(acc0[2], acc0[3]);
                ulonglong2* d1 = reinterpret_cast<ulonglong2*>(dst1);
                d1[0] = make_ulonglong2(acc1[0], acc1[1]);
                d1[1] = make_ulonglong2(acc1[2], acc1[3]);
            }
        } else {
            // === root matmul (32 pairs x 4 slices): starts immediately ===
            u64 acc0[4] = {0, 0, 0, 0}, acc1[4] = {0, 0, 0, 0};
            const float* Wl = &s->R[l][0][0];
            #pragma unroll
            for (int k0 = 0; k0 < 32; k0 += 4) {
                float4 l04 = *reinterpret_cast<const float4*>(aL0 + k0);
                float4 l14 = *reinterpret_cast<const float4*>(aL1 + k0);
                #pragma unroll
                for (int kq = 0; kq < 4; kq++) {
                    u64 a0 = pack2((&l04.x)[kq]);
                    u64 a1 = pack2((&l14.x)[kq]);
                    const ulonglong2* w2 =
                        reinterpret_cast<const ulonglong2*>(Wl + (k0 + kq) * 32 + cc8);
                    ulonglong2 wA = w2[0], wB = w2[1];
                    fma2(acc0[0], a0, wA.x); fma2(acc0[1], a0, wA.y);
                    fma2(acc0[2], a0, wB.x); fma2(acc0[3], a0, wB.y);
                    fma2(acc1[0], a1, wA.x); fma2(acc1[1], a1, wA.y);
                    fma2(acc1[2], a1, wB.x); fma2(acc1[3], a1, wB.y);
                }
            }
            const ulonglong2* bb =
                reinterpret_cast<const ulonglong2*>(&s->bias[l][cc8]);
            ulonglong2 b0 = bb[0], b1 = bb[1];
            add2(acc0[0], b0.x); add2(acc0[1], b0.y);
            add2(acc0[2], b1.x); add2(acc0[3], b1.y);
            add2(acc1[0], b0.x); add2(acc1[1], b0.y);
            add2(acc1[2], b1.x); add2(acc1[3], b1.y);
            ulonglong2* d0 = reinterpret_cast<ulonglong2*>(dst0);
            d0[0] = make_ulonglong2(acc0[0], acc0[1]);
            d0[1] = make_ulonglong2(acc0[2], acc0[3]);
            ulonglong2* d1 = reinterpret_cast<ulonglong2*>(dst1);
            d1[0] = make_ulonglong2(acc1[0], acc1[1]);
            d1[1] = make_ulonglong2(acc1[2], acc1[3]);
        }
        __syncthreads();

        // Phase C: combine + ReLU + LayerNorm (64 nodes x 4 groups of 8 ch).
        {
            float h[8];
            const float4* a0 = reinterpret_cast<const float4*>(&s->AW[0][rij][ch0]);
            const float4* a1 = reinterpret_cast<const float4*>(&s->AW[1][rij][ch0]);
            const float4* a2 = reinterpret_cast<const float4*>(&s->AW[2][rik][ch0]);
            const float4* hr = reinterpret_cast<const float4*>(&s->Hroot[nd][ch0]);
            #pragma unroll
            for (int q4 = 0; q4 < 2; q4++) {
                float4 v0 = a0[q4], v1 = a1[q4], v2 = a2[q4], vr = hr[q4];
                h[q4 * 4 + 0] = v0.x + v1.x + v2.x + vr.x;
                h[q4 * 4 + 1] = v0.y + v1.y + v2.y + vr.y;
                h[q4 * 4 + 2] = v0.z + v1.z + v2.z + vr.z;
                h[q4 * 4 + 3] = v0.w + v1.w + v2.w + vr.w;
            }
            float ssum = 0.0f, sq = 0.0f;
            #pragma unroll
            for (int q = 0; q < 8; q++) {
                h[q] = fmaxf(h[q], 0.0f);
                ssum += h[q];
                sq   += h[q] * h[q];
            }
            ssum += __shfl_xor_sync(0xffffffffu, ssum, 1);
            sq   += __shfl_xor_sync(0xffffffffu, sq, 1);
            ssum += __shfl_xor_sync(0xffffffffu, ssum, 2);
            sq   += __shfl_xor_sync(0xffffffffu, sq, 2);
            float mu  = ssum * (1.0f / 32.0f);
            float var = sq * (1.0f / 32.0f) - mu * mu;
            float rs  = rsqrtf(var + LN_EPS);
            #pragma unroll
            for (int q = 0; q < 8; q++) {
                int c = ch0 + q;
                s->xs[nd][c] = (h[q] - mu) * rs * s->lng[c] + s->lnb[c];
            }
        }
        __syncthreads();
    }

    // ---- output: three axis-means over the 4x4x4 frame -> (48, 32) ----
    float* outb = out + (size_t)b * 48 * 32;
    #pragma unroll
    for (int v = tid; v < 1536; v += TPB) {
        int o = v >> 5, c = v & 31;
        float val;
        if (o < 16) {               // mean over i; o = j*4+k
            val = s->xs[o][c] + s->xs[o + 16][c] + s->xs[o + 32][c] + s->xs[o + 48][c];
        } else if (o < 32) {        // mean over j; (o-16) = i*4+k
            int oo = o - 16; int base = (oo >> 2) * 16 + (oo & 3);
            val = s->xs[base][c] + s->xs[base + 4][c] + s->xs[base + 8][c] + s->xs[base + 12][c];
        } else {                    // mean over k; (o-32) = i*4+j
            int oo = o - 32; int base = (oo >> 2) * 16 + (oo & 3) * 4;
            val = s->xs[base][c] + s->xs[base + 1][c] + s->xs[base + 2][c] + s->xs[base + 3][c];
        }
        outb[o * 32 + c] = val * 0.25f;
    }
}

extern "C" void kernel_launch(void* const* d_in, const int* in_sizes, int n_in,
                              void* d_out, int out_size) {
    const float* xx        = (const float*)d_in[0];
    const float* ss        = (const float*)d_in[1];
    const float* W_f       = (const float*)d_in[2];
    const float* b_f       = (const float*)d_in[3];
    const float* conv_w    = (const float*)d_in[4];
    const float* conv_root = (const float*)d_in[5];
    const float* conv_bias = (const float*)d_in[6];
    const float* ln_g      = (const float*)d_in[7];
    const float* ln_b      = (const float*)d_in[8];
    // d_in[9]/d_in[10] (src/dst) unused: aggregation has a closed form.

    const int B = in_sizes[1];

    cudaFuncSetAttribute(gnn_frame0_kernel,
                         cudaFuncAttributeMaxDynamicSharedMemorySize,
                         (int)sizeof(Smem));
    gnn_frame0_kernel<<<B, TPB, sizeof(Smem)>>>(
        xx, ss, W_f, b_f, conv_w, conv_root, conv_bias, ln_g, ln_b,
        (float*)d_out);
}

// round 13
// speedup vs baseline: 1.0554x; 1.0262x over previous
#include <cuda_runtime.h>
#include <cstdint>

#define TPB 256
#define NLAYER 4
#define LN_EPS 1e-5f

typedef unsigned long long u64;

// Packed fp32-pair ops (Blackwell f32x2 pipe; ptxas never auto-fuses these).
__device__ __forceinline__ void fma2(u64& acc, u64 a, u64 w) {
    asm("fma.rn.f32x2 %0, %1, %2, %0;" : "+l"(acc) : "l"(a), "l"(w));
}
__device__ __forceinline__ u64 pack2(float v) {
    u64 r; asm("mov.b64 %0, {%1, %1};" : "=l"(r) : "f"(v)); return r;
}
__device__ __forceinline__ void mul2(u64& a, u64 b) {
    asm("mul.rn.f32x2 %0, %0, %1;" : "+l"(a) : "l"(b));
}
__device__ __forceinline__ void add2(u64& a, u64 b) {
    asm("add.rn.f32x2 %0, %0, %1;" : "+l"(a) : "l"(b));
}

__device__ __forceinline__ uint32_t s2u(const void* p) {
    uint32_t a;
    asm("{ .reg .u64 t; cvta.to.shared.u64 t, %1; cvt.u32.u64 %0, t; }"
        : "=r"(a) : "l"(p));
    return a;
}

// Spin-wait on mbarrier phase 0 with acquire (we read TMA-written smem after).
__device__ __forceinline__ void mbar_wait0(uint32_t mb) {
    asm volatile(
        "{\n\t"
        ".reg .pred P;\n\t"
        "WAITLP%=:\n\t"
        "mbarrier.try_wait.parity.acquire.cta.shared::cta.b64 P, [%0], 0;\n\t"
        "@P bra WAITDN%=;\n\t"
        "bra WAITLP%=;\n\t"
        "WAITDN%=:\n\t"
        "}"
        :: "r"(mb) : "memory");
}

// ~99 KB shared -> 2 blocks/SM. All hot arrays stride-36 rows (16B aligned).
struct __align__(16) Smem {
    float R[NLAYER][32][32];        // conv_root   (TMA-staged, 16 KB)
    float W[NLAYER][3][32][32];     // conv_w      (TMA-staged, 48 KB, adjacent)
    float bias[NLAYER][32];
    float Wf[6][32];
    float bf[32], lng[32], lnb[32];
    float xs[64][36];               // node features
    float Lij[16][36];              // line sums over k, rows (i*4+j)
    float Lik[16][36];              // line sums over j, rows (i*4+k)
    float Si[4][36];                // plane sums over (j,k)
    float Sj[4][36];                // plane sums over (i,k)
    float Sk[4][36];                // plane sums over (i,j)
    float AW[3][16][36];            // agg_r @ W_r
    float Hroot[64][36];            // x @ R + bias
    float zero[36];                 // guard operand for inactive threads
    alignas(8) u64 mbar;            // TMA completion barrier
};

__global__ __launch_bounds__(TPB) void gnn_frame0_kernel(
    const float* __restrict__ xx, const float* __restrict__ ss,
    const float* __restrict__ W_f, const float* __restrict__ b_f,
    const float* __restrict__ conv_w, const float* __restrict__ conv_root,
    const float* __restrict__ conv_bias, const float* __restrict__ ln_g,
    const float* __restrict__ ln_b, float* __restrict__ out)
{
    extern __shared__ __align__(16) unsigned char smem_raw[];
    Smem* s = reinterpret_cast<Smem*>(smem_raw);
    const int tid = threadIdx.x;
    const int b = blockIdx.x;
    const uint32_t mb = s2u(&s->mbar);

    // ---- async bulk staging of R (16KB) + W (48KB); no LSU involvement ----
    if (tid == 0) {
        asm volatile("mbarrier.init.shared.b64 [%0], %1;" :: "r"(mb), "r"(1) : "memory");
        asm volatile("fence.proxy.async.shared::cta;" ::: "memory");
        asm volatile("mbarrier.arrive.expect_tx.shared.b64 _, [%0], %1;"
                     :: "r"(mb), "r"(65536) : "memory");
        uint32_t dR = s2u(&s->R[0][0][0]);
        uint32_t dW = s2u(&s->W[0][0][0][0]);
        asm volatile(
            "cp.async.bulk.shared::cta.global.mbarrier::complete_tx::bytes [%0], [%1], %2, [%3];"
            :: "r"(dR), "l"(conv_root), "r"(16384), "r"(mb) : "memory");
        asm volatile(
            "cp.async.bulk.shared::cta.global.mbarrier::complete_tx::bytes [%0], [%1], %2, [%3];"
            :: "r"(dW), "l"(conv_w), "r"(49152), "r"(mb) : "memory");
    }
    // small tables: scalar loads by other warps, concurrent with the bulk copy
    if (tid >= 32 && tid < 64) {
        reinterpret_cast<float4*>(&s->bias[0][0])[tid - 32] =
            reinterpret_cast<const float4*>(conv_bias)[tid - 32];
    } else if (tid >= 64 && tid < 112) {
        reinterpret_cast<float4*>(&s->Wf[0][0])[tid - 64] =
            reinterpret_cast<const float4*>(W_f)[tid - 64];
    } else if (tid >= 112 && tid < 144) {
        s->bf[tid - 112] = b_f[tid - 112];
    } else if (tid >= 144 && tid < 176) {
        s->lng[tid - 144] = ln_g[tid - 144];
    } else if (tid >= 176 && tid < 208) {
        s->lnb[tid - 176] = ln_b[tid - 176];
    } else if (tid >= 208 && tid < 244) {
        s->zero[tid - 208] = 0.0f;
    }

    // thread -> (node, 8-channel group) for init / combine phases
    const int nd  = tid >> 2;
    const int ch0 = (tid & 3) * 8;
    const int ii = nd >> 4, jj = (nd >> 2) & 3, kk = nd & 3;
    const int rij = (ii << 2) | jj;
    const int rik = (ii << 2) | kk;

    __syncthreads();   // small tables + mbarrier.init visible

    // ---- initial features (frame t=0): x0 = feats @ W_f + b_f ----
    {
        const float fi = ii * (1.0f / 3.0f);
        const float fj = jj * (1.0f / 3.0f);
        const float fk = kk * (1.0f / 3.0f);
        const float v  = xx[b * 512 + nd];   // frame 0 = first 64 nodes
        const float m  = ss[b] * 0.125f;     // ss / T
        #pragma unroll
        for (int q = 0; q < 8; q++) {
            int c = ch0 + q;
            s->xs[nd][c] = s->bf[c] + fi * s->Wf[0][c] + fj * s->Wf[1][c]
                         + fk * s->Wf[2][c] + v * s->Wf[4][c] + m * s->Wf[5][c];
        }
    }
    __syncthreads();

    // ---- Phase-B mapping: 56 row-pairs x 4 eighth-slices = 224 threads ----
    // pairs 0..23  -> AW (warps 0..2), pairs 24..55 -> root (warps 3..6)
    const int pairIdx = tid >> 2;
    const int cc8 = (tid & 3) * 8;
    const float* aP  = s->zero;
    const float* aL0 = s->zero;
    const float* aL1 = s->zero;
    float* dst0 = s->zero;             // inactive threads never store
    float* dst1 = s->zero;
    int  wOff = 0;
    bool isRoot = false;
    if (tid < 224) {
        if (pairIdx < 24) {
            int r = pairIdx >> 3, t = pairIdx & 7;
            int rowA, rowB;
            wOff = r * 1024;
            if (r == 0) {            // rows i*4+j; pair same i (shares Si)
                rowA = 2 * t; rowB = 2 * t + 1;
                aP = s->Si[t >> 1]; aL0 = s->Lij[rowA]; aL1 = s->Lij[rowB];
            } else if (r == 1) {     // pair same j, i and i+1 (shares Sj)
                int j = t & 3, i0 = (t >> 2) * 2;
                rowA = i0 * 4 + j; rowB = (i0 + 1) * 4 + j;
                aP = s->Sj[j]; aL0 = s->Lij[rowA]; aL1 = s->Lij[rowB];
            } else {                 // pair same k, i and i+1 (shares Sk)
                int k = t & 3, i0 = (t >> 2) * 2;
                rowA = i0 * 4 + k; rowB = (i0 + 1) * 4 + k;
                aP = s->Sk[k]; aL0 = s->Lik[rowA]; aL1 = s->Lik[rowB];
            }
            dst0 = &s->AW[r][rowA][cc8];
            dst1 = &s->AW[r][rowB][cc8];
        } else {
            int n0 = (pairIdx - 24) * 2;
            aL0 = s->xs[n0]; aL1 = s->xs[n0 + 1];
            dst0 = &s->Hroot[n0][cc8];
            dst1 = &s->Hroot[n0 + 1][cc8];
            isRoot = true;
        }
    }

    // ---- 4 R-GCN layers ----
    for (int l = 0; l < NLAYER; l++) {
        // Phase A: line sums (512 items) + plane sums (384 items), one sync.
        // Runs before the TMA wait in layer 0 -> staging latency is hidden.
        #pragma unroll
        for (int v = tid; v < 512; v += TPB) {
            int rr = v >> 5, c = v & 31;
            s->Lij[rr][c] = s->xs[rr * 4 + 0][c] + s->xs[rr * 4 + 1][c]
                          + s->xs[rr * 4 + 2][c] + s->xs[rr * 4 + 3][c];
            int base = (rr >> 2) * 16 + (rr & 3);
            s->Lik[rr][c] = s->xs[base][c] + s->xs[base + 4][c]
                          + s->xs[base + 8][c] + s->xs[base + 12][c];
        }
        #pragma unroll
        for (int t = tid; t < 384; t += TPB) {
            int which = t >> 7, idx = (t >> 5) & 3, c = t & 31;
            float acc = 0.0f;
            if (which == 0) {
                #pragma unroll
                for (int m = 0; m < 16; m++) acc += s->xs[idx * 16 + m][c];
                s->Si[idx][c] = acc;
            } else if (which == 1) {
                #pragma unroll
                for (int i2 = 0; i2 < 4; i2++)
                    #pragma unroll
                    for (int k2 = 0; k2 < 4; k2++)
                        acc += s->xs[i2 * 16 + idx * 4 + k2][c];
                s->Sj[idx][c] = acc;
            } else {
                #pragma unroll
                for (int i2 = 0; i2 < 4; i2++)
                    #pragma unroll
                    for (int j2 = 0; j2 < 4; j2++)
                        acc += s->xs[i2 * 16 + j2 * 4 + idx][c];
                s->Sk[idx][c] = acc;
            }
        }
        __syncthreads();

        // Phase B: 2 rows x 8 channels per thread; weights loaded once per pair.
        if (tid < 224) {
            if (l == 0) mbar_wait0(mb);   // first weight use: join the TMA
            u64 acc0[4] = {0, 0, 0, 0}, acc1[4] = {0, 0, 0, 0};
            if (!isRoot) {
                const float* Wl = &s->W[l][0][0][0] + wOff;
                #pragma unroll
                for (int k0 = 0; k0 < 32; k0 += 4) {
                    float4 p4  = *reinterpret_cast<const float4*>(aP  + k0);
                    float4 l04 = *reinterpret_cast<const float4*>(aL0 + k0);
                    float4 l14 = *reinterpret_cast<const float4*>(aL1 + k0);
                    #pragma unroll
                    for (int kq = 0; kq < 4; kq++) {
                        float pv = (&p4.x)[kq];
                        u64 a0 = pack2(pv - (&l04.x)[kq]);
                        u64 a1 = pack2(pv - (&l14.x)[kq]);
                        const ulonglong2* w2 =
                            reinterpret_cast<const ulonglong2*>(Wl + (k0 + kq) * 32 + cc8);
                        ulonglong2 wA = w2[0], wB = w2[1];
                        fma2(acc0[0], a0, wA.x); fma2(acc0[1], a0, wA.y);
                        fma2(acc0[2], a0, wB.x); fma2(acc0[3], a0, wB.y);
                        fma2(acc1[0], a1, wA.x); fma2(acc1[1], a1, wA.y);
                        fma2(acc1[2], a1, wB.x); fma2(acc1[3], a1, wB.y);
                    }
                }
                u64 s2 = pack2(1.0f / 12.0f);
                #pragma unroll
                for (int q = 0; q < 4; q++) { mul2(acc0[q], s2); mul2(acc1[q], s2); }
            } else {
                const float* Wl = &s->R[l][0][0];
                #pragma unroll
                for (int k0 = 0; k0 < 32; k0 += 4) {
                    float4 l04 = *reinterpret_cast<const float4*>(aL0 + k0);
                    float4 l14 = *reinterpret_cast<const float4*>(aL1 + k0);
                    #pragma unroll
                    for (int kq = 0; kq < 4; kq++) {
                        u64 a0 = pack2((&l04.x)[kq]);
                        u64 a1 = pack2((&l14.x)[kq]);
                        const ulonglong2* w2 =
                            reinterpret_cast<const ulonglong2*>(Wl + (k0 + kq) * 32 + cc8);
                        ulonglong2 wA = w2[0], wB = w2[1];
                        fma2(acc0[0], a0, wA.x); fma2(acc0[1], a0, wA.y);
                        fma2(acc0[2], a0, wB.x); fma2(acc0[3], a0, wB.y);
                        fma2(acc1[0], a1, wA.x); fma2(acc1[1], a1, wA.y);
                        fma2(acc1[2], a1, wB.x); fma2(acc1[3], a1, wB.y);
                    }
                }
                const ulonglong2* bb =
                    reinterpret_cast<const ulonglong2*>(&s->bias[l][cc8]);
                ulonglong2 b0 = bb[0], b1 = bb[1];
                add2(acc0[0], b0.x); add2(acc0[1], b0.y);
                add2(acc0[2], b1.x); add2(acc0[3], b1.y);
                add2(acc1[0], b0.x); add2(acc1[1], b0.y);
                add2(acc1[2], b1.x); add2(acc1[3], b1.y);
            }
            ulonglong2* d0 = reinterpret_cast<ulonglong2*>(dst0);
            d0[0] = make_ulonglong2(acc0[0], acc0[1]);
            d0[1] = make_ulonglong2(acc0[2], acc0[3]);
            ulonglong2* d1 = reinterpret_cast<ulonglong2*>(dst1);
            d1[0] = make_ulonglong2(acc1[0], acc1[1]);
            d1[1] = make_ulonglong2(acc1[2], acc1[3]);
        }
        __syncthreads();

        // Phase C: combine + ReLU + LayerNorm (64 nodes x 4 groups of 8 ch).
        {
            float h[8];
            const float4* a0 = reinterpret_cast<const float4*>(&s->AW[0][rij][ch0]);
            const float4* a1 = reinterpret_cast<const float4*>(&s->AW[1][rij][ch0]);
            const float4* a2 = reinterpret_cast<const float4*>(&s->AW[2][rik][ch0]);
            const float4* hr = reinterpret_cast<const float4*>(&s->Hroot[nd][ch0]);
            #pragma unroll
            for (int q4 = 0; q4 < 2; q4++) {
                float4 v0 = a0[q4], v1 = a1[q4], v2 = a2[q4], vr = hr[q4];
                h[q4 * 4 + 0] = v0.x + v1.x + v2.x + vr.x;
                h[q4 * 4 + 1] = v0.y + v1.y + v2.y + vr.y;
                h[q4 * 4 + 2] = v0.z + v1.z + v2.z + vr.z;
                h[q4 * 4 + 3] = v0.w + v1.w + v2.w + vr.w;
            }
            float ssum = 0.0f, sq = 0.0f;
            #pragma unroll
            for (int q = 0; q < 8; q++) {
                h[q] = fmaxf(h[q], 0.0f);
                ssum += h[q];
                sq   += h[q] * h[q];
            }
            ssum += __shfl_xor_sync(0xffffffffu, ssum, 1);
            sq   += __shfl_xor_sync(0xffffffffu, sq, 1);
            ssum += __shfl_xor_sync(0xffffffffu, ssum, 2);
            sq   += __shfl_xor_sync(0xffffffffu, sq, 2);
            float mu  = ssum * (1.0f / 32.0f);
            float var = sq * (1.0f / 32.0f) - mu * mu;
            float rs  = rsqrtf(var + LN_EPS);
            const float4* g4 = reinterpret_cast<const float4*>(&s->lng[ch0]);
            const float4* n4 = reinterpret_cast<const float4*>(&s->lnb[ch0]);
            float4 g0 = g4[0], g1 = g4[1], B0 = n4[0], B1 = n4[1];
            float4 o0, o1;
            o0.x = (h[0] - mu) * rs * g0.x + B0.x;
            o0.y = (h[1] - mu) * rs * g0.y + B0.y;
            o0.z = (h[2] - mu) * rs * g0.z + B0.z;
            o0.w = (h[3] - mu) * rs * g0.w + B0.w;
            o1.x = (h[4] - mu) * rs * g1.x + B1.x;
            o1.y = (h[5] - mu) * rs * g1.y + B1.y;
            o1.z = (h[6] - mu) * rs * g1.z + B1.z;
            o1.w = (h[7] - mu) * rs * g1.w + B1.w;
            *reinterpret_cast<float4*>(&s->xs[nd][ch0])     = o0;
            *reinterpret_cast<float4*>(&s->xs[nd][ch0 + 4]) = o1;
        }
        __syncthreads();
    }

    // ---- output: three axis-means over the 4x4x4 frame -> (48, 32) ----
    float* outb = out + (size_t)b * 48 * 32;
    #pragma unroll
    for (int v = tid; v < 1536; v += TPB) {
        int o = v >> 5, c = v & 31;
        float val;
        if (o < 16) {               // mean over i; o = j*4+k
            val = s->xs[o][c] + s->xs[o + 16][c] + s->xs[o + 32][c] + s->xs[o + 48][c];
        } else if (o < 32) {        // mean over j; (o-16) = i*4+k
            int oo = o - 16; int base = (oo >> 2) * 16 + (oo & 3);
            val = s->xs[base][c] + s->xs[base + 4][c] + s->xs[base + 8][c] + s->xs[base + 12][c];
        } else {                    // mean over k; (o-32) = i*4+j
            int oo = o - 32; int base = (oo >> 2) * 16 + (oo & 3) * 4;
            val = s->xs[base][c] + s->xs[base + 1][c] + s->xs[base + 2][c] + s->xs[base + 3][c];
        }
        outb[o * 32 + c] = val * 0.25f;
    }
}

extern "C" void kernel_launch(void* const* d_in, const int* in_sizes, int n_in,
                              void* d_out, int out_size) {
    const float* xx        = (const float*)d_in[0];
    const float* ss        = (const float*)d_in[1];
    const float* W_f       = (const float*)d_in[2];
    const float* b_f       = (const float*)d_in[3];
    const float* conv_w    = (const float*)d_in[4];
    const float* conv_root = (const float*)d_in[5];
    const float* conv_bias = (const float*)d_in[6];
    const float* ln_g      = (const float*)d_in[7];
    const float* ln_b      = (const float*)d_in[8];
    // d_in[9]/d_in[10] (src/dst) unused: aggregation has a closed form.

    const int B = in_sizes[1];

    cudaFuncSetAttribute(gnn_frame0_kernel,
                         cudaFuncAttributeMaxDynamicSharedMemorySize,
                         (int)sizeof(Smem));
    gnn_frame0_kernel<<<B, TPB, sizeof(Smem)>>>(
        xx, ss, W_f, b_f, conv_w, conv_root, conv_bias, ln_g, ln_b,
        (float*)d_out);
}

// round 14
// speedup vs baseline: 1.0702x; 1.0140x over previous
#include <cuda_runtime.h>
#include <cstdint>

#define TPB 512
#define NLAYER 4
#define LN_EPS 1e-5f

typedef unsigned long long u64;

// Packed fp32-pair ops (Blackwell f32x2 pipe; ptxas never auto-fuses these).
__device__ __forceinline__ void fma2(u64& acc, u64 a, u64 w) {
    asm("fma.rn.f32x2 %0, %1, %2, %0;" : "+l"(acc) : "l"(a), "l"(w));
}
__device__ __forceinline__ u64 pack2(float v) {
    u64 r; asm("mov.b64 %0, {%1, %1};" : "=l"(r) : "f"(v)); return r;
}
__device__ __forceinline__ void mul2(u64& a, u64 b) {
    asm("mul.rn.f32x2 %0, %0, %1;" : "+l"(a) : "l"(b));
}
__device__ __forceinline__ void add2(u64& a, u64 b) {
    asm("add.rn.f32x2 %0, %0, %1;" : "+l"(a) : "l"(b));
}

__device__ __forceinline__ uint32_t s2u(const void* p) {
    uint32_t a;
    asm("{ .reg .u64 t; cvta.to.shared.u64 t, %1; cvt.u32.u64 %0, t; }"
        : "=r"(a) : "l"(p));
    return a;
}

// Spin-wait on mbarrier phase 0 with acquire (we read TMA-written smem after).
__device__ __forceinline__ void mbar_wait0(uint32_t mb) {
    asm volatile(
        "{\n\t"
        ".reg .pred P;\n\t"
        "WAITLP%=:\n\t"
        "mbarrier.try_wait.parity.acquire.cta.shared::cta.b64 P, [%0], 0;\n\t"
        "@P bra WAITDN%=;\n\t"
        "bra WAITLP%=;\n\t"
        "WAITDN%=:\n\t"
        "}"
        :: "r"(mb) : "memory");
}

// Per-item mutable state, stride-36 rows (16B aligned). ~31.8 KB each.
struct __align__(16) ItemState {
    float xs[64][36];               // node features
    float Lij[16][36];              // line sums over k, rows (i*4+j)
    float Lik[16][36];              // line sums over j, rows (i*4+k)
    float Si[4][36];                // plane sums over (j,k)
    float Sj[4][36];                // plane sums over (i,k)
    float Sk[4][36];                // plane sums over (i,j)
    float AW[3][16][36];            // agg_r @ W_r
    float Hroot[64][36];            // x @ R + bias
    float zero[36];                 // guard operand (never read on hot path)
};

// ~131 KB shared -> 1 block/SM; grid=128 on 148 SMs, every block gets an SM.
struct __align__(16) Smem {
    float R[NLAYER][32][32];        // conv_root   (TMA-staged, 16 KB)
    float W[NLAYER][3][32][32];     // conv_w      (TMA-staged, 48 KB, adjacent)
    float bias[NLAYER][32];
    float Wf[6][32];
    float bf[32], lng[32], lnb[32];
    ItemState it[2];                // one per batch item (thread groups 0/1)
    alignas(8) u64 mbar;            // TMA completion barrier (shared)
};

__global__ __launch_bounds__(TPB) void gnn_frame0_kernel(
    const float* __restrict__ xx, const float* __restrict__ ss,
    const float* __restrict__ W_f, const float* __restrict__ b_f,
    const float* __restrict__ conv_w, const float* __restrict__ conv_root,
    const float* __restrict__ conv_bias, const float* __restrict__ ln_g,
    const float* __restrict__ ln_b, float* __restrict__ out)
{
    extern __shared__ __align__(16) unsigned char smem_raw[];
    Smem* s = reinterpret_cast<Smem*>(smem_raw);
    const int tid = threadIdx.x;
    const int g   = tid >> 8;          // item group 0/1
    const int t   = tid & 255;         // thread id within group
    const int item = blockIdx.x * 2 + g;
    ItemState* it = &s->it[g];
    const uint32_t mb = s2u(&s->mbar);
    const uint32_t barid = g + 1;      // named barrier 1 or 2, 256 threads each

    // ---- async bulk staging of R+W (64KB, ONCE per block / 2 items) ----
    if (tid == 0) {
        asm volatile("mbarrier.init.shared.b64 [%0], %1;" :: "r"(mb), "r"(1) : "memory");
        asm volatile("fence.proxy.async.shared::cta;" ::: "memory");
        asm volatile("mbarrier.arrive.expect_tx.shared.b64 _, [%0], %1;"
                     :: "r"(mb), "r"(65536) : "memory");
        uint32_t dR = s2u(&s->R[0][0][0]);
        uint32_t dW = s2u(&s->W[0][0][0][0]);
        asm volatile(
            "cp.async.bulk.shared::cta.global.mbarrier::complete_tx::bytes [%0], [%1], %2, [%3];"
            :: "r"(dR), "l"(conv_root), "r"(16384), "r"(mb) : "memory");
        asm volatile(
            "cp.async.bulk.shared::cta.global.mbarrier::complete_tx::bytes [%0], [%1], %2, [%3];"
            :: "r"(dW), "l"(conv_w), "r"(49152), "r"(mb) : "memory");
    }
    // small tables: staged once by group 0's upper warps, concurrent with TMA
    if (g == 0) {
        if (t >= 32 && t < 64) {
            reinterpret_cast<float4*>(&s->bias[0][0])[t - 32] =
                reinterpret_cast<const float4*>(conv_bias)[t - 32];
        } else if (t >= 64 && t < 112) {
            reinterpret_cast<float4*>(&s->Wf[0][0])[t - 64] =
                reinterpret_cast<const float4*>(W_f)[t - 64];
        } else if (t >= 112 && t < 144) {
            s->bf[t - 112] = b_f[t - 112];
        } else if (t >= 144 && t < 176) {
            s->lng[t - 144] = ln_g[t - 144];
        } else if (t >= 176 && t < 208) {
            s->lnb[t - 176] = ln_b[t - 176];
        }
    }
    if (t >= 208 && t < 244) it->zero[t - 208] = 0.0f;   // per-item guard

    // thread -> (node, 8-channel group) for init / combine phases
    const int nd  = t >> 2;
    const int ch0 = (t & 3) * 8;
    const int ii = nd >> 4, jj = (nd >> 2) & 3, kk = nd & 3;
    const int rij = (ii << 2) | jj;
    const int rik = (ii << 2) | kk;

    __syncthreads();   // small tables + mbarrier.init visible to both groups

    // ---- initial features (frame t=0): x0 = feats @ W_f + b_f ----
    {
        const float fi = ii * (1.0f / 3.0f);
        const float fj = jj * (1.0f / 3.0f);
        const float fk = kk * (1.0f / 3.0f);
        const float v  = xx[item * 512 + nd];   // frame 0 = first 64 nodes
        const float m  = ss[item] * 0.125f;     // ss / T
        #pragma unroll
        for (int q = 0; q < 8; q++) {
            int c = ch0 + q;
            it->xs[nd][c] = s->bf[c] + fi * s->Wf[0][c] + fj * s->Wf[1][c]
                          + fk * s->Wf[2][c] + v * s->Wf[4][c] + m * s->Wf[5][c];
        }
    }
    asm volatile("bar.sync %0, 256;" :: "r"(barid) : "memory");

    // ---- Phase-B mapping: 56 row-pairs x 4 eighth-slices = 224 threads ----
    const int pairIdx = t >> 2;
    const int cc8 = (t & 3) * 8;
    const float* aP  = it->zero;
    const float* aL0 = it->zero;
    const float* aL1 = it->zero;
    float* dst0 = it->zero;            // inactive threads never store
    float* dst1 = it->zero;
    int  wOff = 0;
    bool isRoot = false;
    if (t < 224) {
        if (pairIdx < 24) {
            int r = pairIdx >> 3, tt = pairIdx & 7;
            int rowA, rowB;
            wOff = r * 1024;
            if (r == 0) {            // rows i*4+j; pair same i (shares Si)
                rowA = 2 * tt; rowB = 2 * tt + 1;
                aP = it->Si[tt >> 1]; aL0 = it->Lij[rowA]; aL1 = it->Lij[rowB];
            } else if (r == 1) {     // pair same j, i and i+1 (shares Sj)
                int j = tt & 3, i0 = (tt >> 2) * 2;
                rowA = i0 * 4 + j; rowB = (i0 + 1) * 4 + j;
                aP = it->Sj[j]; aL0 = it->Lij[rowA]; aL1 = it->Lij[rowB];
            } else {                 // pair same k, i and i+1 (shares Sk)
                int k = tt & 3, i0 = (tt >> 2) * 2;
                rowA = i0 * 4 + k; rowB = (i0 + 1) * 4 + k;
                aP = it->Sk[k]; aL0 = it->Lik[rowA]; aL1 = it->Lik[rowB];
            }
            dst0 = &it->AW[r][rowA][cc8];
            dst1 = &it->AW[r][rowB][cc8];
        } else {
            int n0 = (pairIdx - 24) * 2;
            aL0 = it->xs[n0]; aL1 = it->xs[n0 + 1];
            dst0 = &it->Hroot[n0][cc8];
            dst1 = &it->Hroot[n0 + 1][cc8];
            isRoot = true;
        }
    }

    // ---- 4 R-GCN layers (each group independent; named barriers only) ----
    for (int l = 0; l < NLAYER; l++) {
        // Phase A: line sums (512 items) + plane sums (384 items), one sync.
        #pragma unroll
        for (int v = t; v < 512; v += 256) {
            int rr = v >> 5, c = v & 31;
            it->Lij[rr][c] = it->xs[rr * 4 + 0][c] + it->xs[rr * 4 + 1][c]
                           + it->xs[rr * 4 + 2][c] + it->xs[rr * 4 + 3][c];
            int base = (rr >> 2) * 16 + (rr & 3);
            it->Lik[rr][c] = it->xs[base][c] + it->xs[base + 4][c]
                           + it->xs[base + 8][c] + it->xs[base + 12][c];
        }
        #pragma unroll
        for (int w = t; w < 384; w += 256) {
            int which = w >> 7, idx = (w >> 5) & 3, c = w & 31;
            float acc = 0.0f;
            if (which == 0) {
                #pragma unroll
                for (int m = 0; m < 16; m++) acc += it->xs[idx * 16 + m][c];
                it->Si[idx][c] = acc;
            } else if (which == 1) {
                #pragma unroll
                for (int i2 = 0; i2 < 4; i2++)
                    #pragma unroll
                    for (int k2 = 0; k2 < 4; k2++)
                        acc += it->xs[i2 * 16 + idx * 4 + k2][c];
                it->Sj[idx][c] = acc;
            } else {
                #pragma unroll
                for (int i2 = 0; i2 < 4; i2++)
                    #pragma unroll
                    for (int j2 = 0; j2 < 4; j2++)
                        acc += it->xs[i2 * 16 + j2 * 4 + idx][c];
                it->Sk[idx][c] = acc;
            }
        }
        asm volatile("bar.sync %0, 256;" :: "r"(barid) : "memory");

        // Phase B: 2 rows x 8 channels per thread; weights loaded once per pair.
        if (t < 224) {
            if (l == 0) mbar_wait0(mb);   // first weight use: join the TMA
            u64 acc0[4] = {0, 0, 0, 0}, acc1[4] = {0, 0, 0, 0};
            if (!isRoot) {
                const float* Wl = &s->W[l][0][0][0] + wOff;
                #pragma unroll
                for (int k0 = 0; k0 < 32; k0 += 4) {
                    float4 p4  = *reinterpret_cast<const float4*>(aP  + k0);
                    float4 l04 = *reinterpret_cast<const float4*>(aL0 + k0);
                    float4 l14 = *reinterpret_cast<const float4*>(aL1 + k0);
                    #pragma unroll
                    for (int kq = 0; kq < 4; kq++) {
                        float pv = (&p4.x)[kq];
                        u64 a0 = pack2(pv - (&l04.x)[kq]);
                        u64 a1 = pack2(pv - (&l14.x)[kq]);
                        const ulonglong2* w2 =
                            reinterpret_cast<const ulonglong2*>(Wl + (k0 + kq) * 32 + cc8);
                        ulonglong2 wA = w2[0], wB = w2[1];
                        fma2(acc0[0], a0, wA.x); fma2(acc0[1], a0, wA.y);
                        fma2(acc0[2], a0, wB.x); fma2(acc0[3], a0, wB.y);
                        fma2(acc1[0], a1, wA.x); fma2(acc1[1], a1, wA.y);
                        fma2(acc1[2], a1, wB.x); fma2(acc1[3], a1, wB.y);
                    }
                }
                u64 s2 = pack2(1.0f / 12.0f);
                #pragma unroll
                for (int q = 0; q < 4; q++) { mul2(acc0[q], s2); mul2(acc1[q], s2); }
            } else {
                const float* Wl = &s->R[l][0][0];
                #pragma unroll
                for (int k0 = 0; k0 < 32; k0 += 4) {
                    float4 l04 = *reinterpret_cast<const float4*>(aL0 + k0);
                    float4 l14 = *reinterpret_cast<const float4*>(aL1 + k0);
                    #pragma unroll
                    for (int kq = 0; kq < 4; kq++) {
                        u64 a0 = pack2((&l04.x)[kq]);
                        u64 a1 = pack2((&l14.x)[kq]);
                        const ulonglong2* w2 =
                            reinterpret_cast<const ulonglong2*>(Wl + (k0 + kq) * 32 + cc8);
                        ulonglong2 wA = w2[0], wB = w2[1];
                        fma2(acc0[0], a0, wA.x); fma2(acc0[1], a0, wA.y);
                        fma2(acc0[2], a0, wB.x); fma2(acc0[3], a0, wB.y);
                        fma2(acc1[0], a1, wA.x); fma2(acc1[1], a1, wA.y);
                        fma2(acc1[2], a1, wB.x); fma2(acc1[3], a1, wB.y);
                    }
                }
                const ulonglong2* bb =
                    reinterpret_cast<const ulonglong2*>(&s->bias[l][cc8]);
                ulonglong2 b0 = bb[0], b1 = bb[1];
                add2(acc0[0], b0.x); add2(acc0[1], b0.y);
                add2(acc0[2], b1.x); add2(acc0[3], b1.y);
                add2(acc1[0], b0.x); add2(acc1[1], b0.y);
                add2(acc1[2], b1.x); add2(acc1[3], b1.y);
            }
            ulonglong2* d0 = reinterpret_cast<ulonglong2*>(dst0);
            d0[0] = make_ulonglong2(acc0[0], acc0[1]);
            d0[1] = make_ulonglong2(acc0[2], acc0[3]);
            ulonglong2* d1 = reinterpret_cast<ulonglong2*>(dst1);
            d1[0] = make_ulonglong2(acc1[0], acc1[1]);
            d1[1] = make_ulonglong2(acc1[2], acc1[3]);
        }
        asm volatile("bar.sync %0, 256;" :: "r"(barid) : "memory");

        // Phase C: combine + ReLU + LayerNorm (64 nodes x 4 groups of 8 ch).
        {
            float h[8];
            const float4* a0 = reinterpret_cast<const float4*>(&it->AW[0][rij][ch0]);
            const float4* a1 = reinterpret_cast<const float4*>(&it->AW[1][rij][ch0]);
            const float4* a2 = reinterpret_cast<const float4*>(&it->AW[2][rik][ch0]);
            const float4* hr = reinterpret_cast<const float4*>(&it->Hroot[nd][ch0]);
            #pragma unroll
            for (int q4 = 0; q4 < 2; q4++) {
                float4 v0 = a0[q4], v1 = a1[q4], v2 = a2[q4], vr = hr[q4];
                h[q4 * 4 + 0] = v0.x + v1.x + v2.x + vr.x;
                h[q4 * 4 + 1] = v0.y + v1.y + v2.y + vr.y;
                h[q4 * 4 + 2] = v0.z + v1.z + v2.z + vr.z;
                h[q4 * 4 + 3] = v0.w + v1.w + v2.w + vr.w;
            }
            float ssum = 0.0f, sq = 0.0f;
            #pragma unroll
            for (int q = 0; q < 8; q++) {
                h[q] = fmaxf(h[q], 0.0f);
                ssum += h[q];
                sq   += h[q] * h[q];
            }
            ssum += __shfl_xor_sync(0xffffffffu, ssum, 1);
            sq   += __shfl_xor_sync(0xffffffffu, sq, 1);
            ssum += __shfl_xor_sync(0xffffffffu, ssum, 2);
            sq   += __shfl_xor_sync(0xffffffffu, sq, 2);
            float mu  = ssum * (1.0f / 32.0f);
            float var = sq * (1.0f / 32.0f) - mu * mu;
            float rs  = rsqrtf(var + LN_EPS);
            const float4* g4 = reinterpret_cast<const float4*>(&s->lng[ch0]);
            const float4* n4 = reinterpret_cast<const float4*>(&s->lnb[ch0]);
            float4 g0 = g4[0], g1 = g4[1], B0 = n4[0], B1 = n4[1];
            float4 o0, o1;
            o0.x = (h[0] - mu) * rs * g0.x + B0.x;
            o0.y = (h[1] - mu) * rs * g0.y + B0.y;
            o0.z = (h[2] - mu) * rs * g0.z + B0.z;
            o0.w = (h[3] - mu) * rs * g0.w + B0.w;
            o1.x = (h[4] - mu) * rs * g1.x + B1.x;
            o1.y = (h[5] - mu) * rs * g1.y + B1.y;
            o1.z = (h[6] - mu) * rs * g1.z + B1.z;
            o1.w = (h[7] - mu) * rs * g1.w + B1.w;
            *reinterpret_cast<float4*>(&it->xs[nd][ch0])     = o0;
            *reinterpret_cast<float4*>(&it->xs[nd][ch0 + 4]) = o1;
        }
        asm volatile("bar.sync %0, 256;" :: "r"(barid) : "memory");
    }

    // ---- output: three axis-means over the 4x4x4 frame -> (48, 32) ----
    float* outb = out + (size_t)item * 48 * 32;
    #pragma unroll
    for (int v = t; v < 1536; v += 256) {
        int o = v >> 5, c = v & 31;
        float val;
        if (o < 16) {               // mean over i; o = j*4+k
            val = it->xs[o][c] + it->xs[o + 16][c] + it->xs[o + 32][c] + it->xs[o + 48][c];
        } else if (o < 32) {        // mean over j; (o-16) = i*4+k
            int oo = o - 16; int base = (oo >> 2) * 16 + (oo & 3);
            val = it->xs[base][c] + it->xs[base + 4][c] + it->xs[base + 8][c] + it->xs[base + 12][c];
        } else {                    // mean over k; (o-32) = i*4+j
            int oo = o - 32; int base = (oo >> 2) * 16 + (oo & 3) * 4;
            val = it->xs[base][c] + it->xs[base + 1][c] + it->xs[base + 2][c] + it->xs[base + 3][c];
        }
        outb[o * 32 + c] = val * 0.25f;
    }
}

extern "C" void kernel_launch(void* const* d_in, const int* in_sizes, int n_in,
                              void* d_out, int out_size) {
    const float* xx        = (const float*)d_in[0];
    const float* ss        = (const float*)d_in[1];
    const float* W_f       = (const float*)d_in[2];
    const float* b_f       = (const float*)d_in[3];
    const float* conv_w    = (const float*)d_in[4];
    const float* conv_root = (const float*)d_in[5];
    const float* conv_bias = (const float*)d_in[6];
    const float* ln_g      = (const float*)d_in[7];
    const float* ln_b      = (const float*)d_in[8];
    // d_in[9]/d_in[10] (src/dst) unused: aggregation has a closed form.

    const int B = in_sizes[1];          // 256 (even)

    cudaFuncSetAttribute(gnn_frame0_kernel,
                         cudaFuncAttributeMaxDynamicSharedMemorySize,
                         (int)sizeof(Smem));
    gnn_frame0_kernel<<<B / 2, TPB, sizeof(Smem)>>>(
        xx, ss, W_f, b_f, conv_w, conv_root, conv_bias, ln_g, ln_b,
        (float*)d_out);
}

// round 15
// speedup vs baseline: 1.2751x; 1.1914x over previous
#include <cuda_runtime.h>
#include <cstdint>

#define TPB 256
#define NLAYER 4
#define LN_EPS 1e-5f

typedef unsigned long long u64;

// Packed fp32-pair ops (Blackwell f32x2 pipe; ptxas never auto-fuses these).
__device__ __forceinline__ void fma2(u64& acc, u64 a, u64 w) {
    asm("fma.rn.f32x2 %0, %1, %2, %0;" : "+l"(acc) : "l"(a), "l"(w));
}
__device__ __forceinline__ u64 pack2(float v) {
    u64 r; asm("mov.b64 %0, {%1, %1};" : "=l"(r) : "f"(v)); return r;
}
__device__ __forceinline__ void mul2(u64& a, u64 b) {
    asm("mul.rn.f32x2 %0, %0, %1;" : "+l"(a) : "l"(b));
}
__device__ __forceinline__ void add2(u64& a, u64 b) {
    asm("add.rn.f32x2 %0, %0, %1;" : "+l"(a) : "l"(b));
}

__device__ __forceinline__ uint32_t s2u(const void* p) {
    uint32_t a;
    asm("{ .reg .u64 t; cvta.to.shared.u64 t, %1; cvt.u32.u64 %0, t; }"
        : "=r"(a) : "l"(p));
    return a;
}

// Spin-wait on mbarrier phase 0 with acquire (we read TMA-written smem after).
__device__ __forceinline__ void mbar_wait0(uint32_t mb) {
    asm volatile(
        "{\n\t"
        ".reg .pred P;\n\t"
        "WAITLP%=:\n\t"
        "mbarrier.try_wait.parity.acquire.cta.shared::cta.b64 P, [%0], 0;\n\t"
        "@P bra WAITDN%=;\n\t"
        "bra WAITLP%=;\n\t"
        "WAITDN%=:\n\t"
        "}"
        :: "r"(mb) : "memory");
}

// Per-item mutable state, stride-36 rows (16B aligned). ~31.8 KB each.
struct __align__(16) ItemState {
    float xs[64][36];               // node features
    float Lij[16][36];              // line sums over k, rows (i*4+j)
    float Lik[16][36];              // line sums over j, rows (i*4+k)
    float Si[4][36];                // plane sums over (j,k)
    float Sj[4][36];                // plane sums over (i,k)
    float Sk[4][36];                // plane sums over (i,j)
    float AW[3][16][36];            // agg_r @ W_r
    float Hroot[64][36];            // x @ R + bias
};

// ~131 KB shared -> 1 block/SM; grid=128 on 148 SMs.
struct __align__(16) Smem {
    float R[NLAYER][32][32];        // conv_root   (TMA-staged, 16 KB)
    float W[NLAYER][3][32][32];     // conv_w      (TMA-staged, 48 KB, adjacent)
    float bias[NLAYER][32];
    float Wf[6][32];
    float bf[32], lng[32], lnb[32];
    ItemState it[2];                // both items processed by ALL threads
    float zero[36];                 // guard operand for inactive threads
    alignas(8) u64 mbar;            // TMA completion barrier
};

__global__ __launch_bounds__(TPB, 1) void gnn_frame0_kernel(
    const float* __restrict__ xx, const float* __restrict__ ss,
    const float* __restrict__ W_f, const float* __restrict__ b_f,
    const float* __restrict__ conv_w, const float* __restrict__ conv_root,
    const float* __restrict__ conv_bias, const float* __restrict__ ln_g,
    const float* __restrict__ ln_b, float* __restrict__ out)
{
    extern __shared__ __align__(16) unsigned char smem_raw[];
    Smem* s = reinterpret_cast<Smem*>(smem_raw);
    const int t = threadIdx.x;
    const int item0 = blockIdx.x * 2;
    ItemState* it0 = &s->it[0];
    ItemState* it1 = &s->it[1];
    const uint32_t mb = s2u(&s->mbar);

    // ---- async bulk staging of R+W (64KB, once per block / 2 items) ----
    if (t == 0) {
        asm volatile("mbarrier.init.shared.b64 [%0], %1;" :: "r"(mb), "r"(1) : "memory");
        asm volatile("fence.proxy.async.shared::cta;" ::: "memory");
        asm volatile("mbarrier.arrive.expect_tx.shared.b64 _, [%0], %1;"
                     :: "r"(mb), "r"(65536) : "memory");
        uint32_t dR = s2u(&s->R[0][0][0]);
        uint32_t dW = s2u(&s->W[0][0][0][0]);
        asm volatile(
            "cp.async.bulk.shared::cta.global.mbarrier::complete_tx::bytes [%0], [%1], %2, [%3];"
            :: "r"(dR), "l"(conv_root), "r"(16384), "r"(mb) : "memory");
        asm volatile(
            "cp.async.bulk.shared::cta.global.mbarrier::complete_tx::bytes [%0], [%1], %2, [%3];"
            :: "r"(dW), "l"(conv_w), "r"(49152), "r"(mb) : "memory");
    }
    // small tables: scalar loads, concurrent with the bulk copy
    if (t >= 32 && t < 64) {
        reinterpret_cast<float4*>(&s->bias[0][0])[t - 32] =
            reinterpret_cast<const float4*>(conv_bias)[t - 32];
    } else if (t >= 64 && t < 112) {
        reinterpret_cast<float4*>(&s->Wf[0][0])[t - 64] =
            reinterpret_cast<const float4*>(W_f)[t - 64];
    } else if (t >= 112 && t < 144) {
        s->bf[t - 112] = b_f[t - 112];
    } else if (t >= 144 && t < 176) {
        s->lng[t - 144] = ln_g[t - 144];
    } else if (t >= 176 && t < 208) {
        s->lnb[t - 176] = ln_b[t - 176];
    } else if (t >= 208 && t < 244) {
        s->zero[t - 208] = 0.0f;
    }

    // thread -> (node, 8-channel group) for init / combine phases
    const int nd  = t >> 2;
    const int ch0 = (t & 3) * 8;
    const int ii = nd >> 4, jj = (nd >> 2) & 3, kk = nd & 3;
    const int rij = (ii << 2) | jj;
    const int rik = (ii << 2) | kk;

    __syncthreads();   // small tables + mbarrier.init visible

    // ---- initial features for BOTH items ----
    {
        const float fi = ii * (1.0f / 3.0f);
        const float fj = jj * (1.0f / 3.0f);
        const float fk = kk * (1.0f / 3.0f);
        const float v0 = xx[item0 * 512 + nd];
        const float v1 = xx[(item0 + 1) * 512 + nd];
        const float m0 = ss[item0] * 0.125f;
        const float m1 = ss[item0 + 1] * 0.125f;
        #pragma unroll
        for (int q = 0; q < 8; q++) {
            int c = ch0 + q;
            float base = s->bf[c] + fi * s->Wf[0][c] + fj * s->Wf[1][c]
                       + fk * s->Wf[2][c];
            it0->xs[nd][c] = base + v0 * s->Wf[4][c] + m0 * s->Wf[5][c];
            it1->xs[nd][c] = base + v1 * s->Wf[4][c] + m1 * s->Wf[5][c];
        }
    }
    __syncthreads();

    // ---- Phase-B mapping: 56 row-pairs x 4 eighth-slices = 224 threads ----
    const int pairIdx = t >> 2;
    const int cc8 = (t & 3) * 8;
    int rowA = 0, rowB = 0;             // row indices (same for both items)
    int pOffP = -1, pOffL0 = 0, pOffL1 = 0, dOff0 = 0, dOff1 = 0;
    int  wOff = 0;
    bool isRoot = false;
    if (t < 224) {
        if (pairIdx < 24) {
            int r = pairIdx >> 3, tt = pairIdx & 7;
            wOff = r * 1024;
            if (r == 0) {
                rowA = 2 * tt; rowB = 2 * tt + 1;
                pOffP  = (int)(it0->Si[tt >> 1] - (float*)it0);
                pOffL0 = (int)(it0->Lij[rowA] - (float*)it0);
                pOffL1 = (int)(it0->Lij[rowB] - (float*)it0);
            } else if (r == 1) {
                int j = tt & 3, i0 = (tt >> 2) * 2;
                rowA = i0 * 4 + j; rowB = (i0 + 1) * 4 + j;
                pOffP  = (int)(it0->Sj[j] - (float*)it0);
                pOffL0 = (int)(it0->Lij[rowA] - (float*)it0);
                pOffL1 = (int)(it0->Lij[rowB] - (float*)it0);
            } else {
                int k = tt & 3, i0 = (tt >> 2) * 2;
                rowA = i0 * 4 + k; rowB = (i0 + 1) * 4 + k;
                pOffP  = (int)(it0->Sk[k] - (float*)it0);
                pOffL0 = (int)(it0->Lik[rowA] - (float*)it0);
                pOffL1 = (int)(it0->Lik[rowB] - (float*)it0);
            }
            dOff0 = (int)(&it0->AW[r][rowA][cc8] - (float*)it0);
            dOff1 = (int)(&it0->AW[r][rowB][cc8] - (float*)it0);
        } else {
            int n0 = (pairIdx - 24) * 2;
            pOffL0 = (int)(it0->xs[n0] - (float*)it0);
            pOffL1 = (int)(it0->xs[n0 + 1] - (float*)it0);
            dOff0 = (int)(&it0->Hroot[n0][cc8] - (float*)it0);
            dOff1 = (int)(&it0->Hroot[n0 + 1][cc8] - (float*)it0);
            isRoot = true;
        }
    }
    const float* b0f = (const float*)it0;
    const float* b1f = (const float*)it1;

    // ---- 4 R-GCN layers; all phases process BOTH items per thread ----
    for (int l = 0; l < NLAYER; l++) {
        // Phase A: line sums + plane sums for both items (independent chains).
        #pragma unroll
        for (int v = t; v < 512; v += TPB) {
            int rr = v >> 5, c = v & 31;
            int base = (rr >> 2) * 16 + (rr & 3);
            it0->Lij[rr][c] = it0->xs[rr * 4 + 0][c] + it0->xs[rr * 4 + 1][c]
                            + it0->xs[rr * 4 + 2][c] + it0->xs[rr * 4 + 3][c];
            it1->Lij[rr][c] = it1->xs[rr * 4 + 0][c] + it1->xs[rr * 4 + 1][c]
                            + it1->xs[rr * 4 + 2][c] + it1->xs[rr * 4 + 3][c];
            it0->Lik[rr][c] = it0->xs[base][c] + it0->xs[base + 4][c]
                            + it0->xs[base + 8][c] + it0->xs[base + 12][c];
            it1->Lik[rr][c] = it1->xs[base][c] + it1->xs[base + 4][c]
                            + it1->xs[base + 8][c] + it1->xs[base + 12][c];
        }
        #pragma unroll
        for (int w = t; w < 384; w += TPB) {
            int which = w >> 7, idx = (w >> 5) & 3, c = w & 31;
            float a0 = 0.0f, a1 = 0.0f;
            if (which == 0) {
                #pragma unroll
                for (int m = 0; m < 16; m++) {
                    a0 += it0->xs[idx * 16 + m][c];
                    a1 += it1->xs[idx * 16 + m][c];
                }
                it0->Si[idx][c] = a0; it1->Si[idx][c] = a1;
            } else if (which == 1) {
                #pragma unroll
                for (int i2 = 0; i2 < 4; i2++)
                    #pragma unroll
                    for (int k2 = 0; k2 < 4; k2++) {
                        a0 += it0->xs[i2 * 16 + idx * 4 + k2][c];
                        a1 += it1->xs[i2 * 16 + idx * 4 + k2][c];
                    }
                it0->Sj[idx][c] = a0; it1->Sj[idx][c] = a1;
            } else {
                #pragma unroll
                for (int i2 = 0; i2 < 4; i2++)
                    #pragma unroll
                    for (int j2 = 0; j2 < 4; j2++) {
                        a0 += it0->xs[i2 * 16 + j2 * 4 + idx][c];
                        a1 += it1->xs[i2 * 16 + j2 * 4 + idx][c];
                    }
                it0->Sk[idx][c] = a0; it1->Sk[idx][c] = a1;
            }
        }
        __syncthreads();

        // Phase B: weights loaded ONCE feed both items (16 FFMA2 chains).
        if (t < 224) {
            if (l == 0) mbar_wait0(mb);   // first weight use: join the TMA
            u64 xA0[4] = {0,0,0,0}, xB0[4] = {0,0,0,0};   // item0 rows A,B
            u64 xA1[4] = {0,0,0,0}, xB1[4] = {0,0,0,0};   // item1 rows A,B
            if (!isRoot) {
                const float* Wl = &s->W[l][0][0][0] + wOff;
                #pragma unroll
                for (int k0 = 0; k0 < 32; k0 += 4) {
                    float4 p0 = *reinterpret_cast<const float4*>(b0f + pOffP + k0);
                    float4 q0 = *reinterpret_cast<const float4*>(b0f + pOffL0 + k0);
                    float4 q1 = *reinterpret_cast<const float4*>(b0f + pOffL1 + k0);
                    float4 p1 = *reinterpret_cast<const float4*>(b1f + pOffP + k0);
                    float4 r0 = *reinterpret_cast<const float4*>(b1f + pOffL0 + k0);
                    float4 r1 = *reinterpret_cast<const float4*>(b1f + pOffL1 + k0);
                    #pragma unroll
                    for (int kq = 0; kq < 4; kq++) {
                        const ulonglong2* w2 =
                            reinterpret_cast<const ulonglong2*>(Wl + (k0 + kq) * 32 + cc8);
                        ulonglong2 wA = w2[0], wB = w2[1];
                        float pv0 = (&p0.x)[kq], pv1 = (&p1.x)[kq];
                        u64 aA0 = pack2(pv0 - (&q0.x)[kq]);
                        u64 aB0 = pack2(pv0 - (&q1.x)[kq]);
                        u64 aA1 = pack2(pv1 - (&r0.x)[kq]);
                        u64 aB1 = pack2(pv1 - (&r1.x)[kq]);
                        fma2(xA0[0], aA0, wA.x); fma2(xA0[1], aA0, wA.y);
                        fma2(xA0[2], aA0, wB.x); fma2(xA0[3], aA0, wB.y);
                        fma2(xB0[0], aB0, wA.x); fma2(xB0[1], aB0, wA.y);
                        fma2(xB0[2], aB0, wB.x); fma2(xB0[3], aB0, wB.y);
                        fma2(xA1[0], aA1, wA.x); fma2(xA1[1], aA1, wA.y);
                        fma2(xA1[2], aA1, wB.x); fma2(xA1[3], aA1, wB.y);
                        fma2(xB1[0], aB1, wA.x); fma2(xB1[1], aB1, wA.y);
                        fma2(xB1[2], aB1, wB.x); fma2(xB1[3], aB1, wB.y);
                    }
                }
                u64 s2 = pack2(1.0f / 12.0f);
                #pragma unroll
                for (int q = 0; q < 4; q++) {
                    mul2(xA0[q], s2); mul2(xB0[q], s2);
                    mul2(xA1[q], s2); mul2(xB1[q], s2);
                }
            } else {
                const float* Wl = &s->R[l][0][0];
                #pragma unroll
                for (int k0 = 0; k0 < 32; k0 += 4) {
                    float4 q0 = *reinterpret_cast<const float4*>(b0f + pOffL0 + k0);
                    float4 q1 = *reinterpret_cast<const float4*>(b0f + pOffL1 + k0);
                    float4 r0 = *reinterpret_cast<const float4*>(b1f + pOffL0 + k0);
                    float4 r1 = *reinterpret_cast<const float4*>(b1f + pOffL1 + k0);
                    #pragma unroll
                    for (int kq = 0; kq < 4; kq++) {
                        const ulonglong2* w2 =
                            reinterpret_cast<const ulonglong2*>(Wl + (k0 + kq) * 32 + cc8);
                        ulonglong2 wA = w2[0], wB = w2[1];
                        u64 aA0 = pack2((&q0.x)[kq]);
                        u64 aB0 = pack2((&q1.x)[kq]);
                        u64 aA1 = pack2((&r0.x)[kq]);
                        u64 aB1 = pack2((&r1.x)[kq]);
                        fma2(xA0[0], aA0, wA.x); fma2(xA0[1], aA0, wA.y);
                        fma2(xA0[2], aA0, wB.x); fma2(xA0[3], aA0, wB.y);
                        fma2(xB0[0], aB0, wA.x); fma2(xB0[1], aB0, wA.y);
                        fma2(xB0[2], aB0, wB.x); fma2(xB0[3], aB0, wB.y);
                        fma2(xA1[0], aA1, wA.x); fma2(xA1[1], aA1, wA.y);
                        fma2(xA1[2], aA1, wB.x); fma2(xA1[3], aA1, wB.y);
                        fma2(xB1[0], aB1, wA.x); fma2(xB1[1], aB1, wA.y);
                        fma2(xB1[2], aB1, wB.x); fma2(xB1[3], aB1, wB.y);
                    }
                }
                const ulonglong2* bb =
                    reinterpret_cast<const ulonglong2*>(&s->bias[l][cc8]);
                ulonglong2 bA = bb[0], bB = bb[1];
                add2(xA0[0], bA.x); add2(xA0[1], bA.y);
                add2(xA0[2], bB.x); add2(xA0[3], bB.y);
                add2(xB0[0], bA.x); add2(xB0[1], bA.y);
                add2(xB0[2], bB.x); add2(xB0[3], bB.y);
                add2(xA1[0], bA.x); add2(xA1[1], bA.y);
                add2(xA1[2], bB.x); add2(xA1[3], bB.y);
                add2(xB1[0], bA.x); add2(xB1[1], bA.y);
                add2(xB1[2], bB.x); add2(xB1[3], bB.y);
            }
            ulonglong2* dA0 = reinterpret_cast<ulonglong2*>((float*)it0 + dOff0);
            dA0[0] = make_ulonglong2(xA0[0], xA0[1]);
            dA0[1] = make_ulonglong2(xA0[2], xA0[3]);
            ulonglong2* dB0 = reinterpret_cast<ulonglong2*>((float*)it0 + dOff1);
            dB0[0] = make_ulonglong2(xB0[0], xB0[1]);
            dB0[1] = make_ulonglong2(xB0[2], xB0[3]);
            ulonglong2* dA1 = reinterpret_cast<ulonglong2*>((float*)it1 + dOff0);
            dA1[0] = make_ulonglong2(xA1[0], xA1[1]);
            dA1[1] = make_ulonglong2(xA1[2], xA1[3]);
            ulonglong2* dB1 = reinterpret_cast<ulonglong2*>((float*)it1 + dOff1);
            dB1[0] = make_ulonglong2(xB1[0], xB1[1]);
            dB1[1] = make_ulonglong2(xB1[2], xB1[3]);
        }
        __syncthreads();

        // Phase C: combine + ReLU + LayerNorm for both items.
        {
            const float4* g4 = reinterpret_cast<const float4*>(&s->lng[ch0]);
            const float4* n4 = reinterpret_cast<const float4*>(&s->lnb[ch0]);
            float4 g0 = g4[0], g1 = g4[1], N0 = n4[0], N1 = n4[1];
            #pragma unroll
            for (int g2 = 0; g2 < 2; g2++) {
                ItemState* itc = (g2 == 0) ? it0 : it1;
                float h[8];
                const float4* a0 = reinterpret_cast<const float4*>(&itc->AW[0][rij][ch0]);
                const float4* a1 = reinterpret_cast<const float4*>(&itc->AW[1][rij][ch0]);
                const float4* a2 = reinterpret_cast<const float4*>(&itc->AW[2][rik][ch0]);
                const float4* hr = reinterpret_cast<const float4*>(&itc->Hroot[nd][ch0]);
                #pragma unroll
                for (int q4 = 0; q4 < 2; q4++) {
                    float4 v0 = a0[q4], v1 = a1[q4], v2 = a2[q4], vr = hr[q4];
                    h[q4 * 4 + 0] = v0.x + v1.x + v2.x + vr.x;
                    h[q4 * 4 + 1] = v0.y + v1.y + v2.y + vr.y;
                    h[q4 * 4 + 2] = v0.z + v1.z + v2.z + vr.z;
                    h[q4 * 4 + 3] = v0.w + v1.w + v2.w + vr.w;
                }
                float ssum = 0.0f, sq = 0.0f;
                #pragma unroll
                for (int q = 0; q < 8; q++) {
                    h[q] = fmaxf(h[q], 0.0f);
                    ssum += h[q];
                    sq   += h[q] * h[q];
                }
                ssum += __shfl_xor_sync(0xffffffffu, ssum, 1);
                sq   += __shfl_xor_sync(0xffffffffu, sq, 1);
                ssum += __shfl_xor_sync(0xffffffffu, ssum, 2);
                sq   += __shfl_xor_sync(0xffffffffu, sq, 2);
                float mu  = ssum * (1.0f / 32.0f);
                float var = sq * (1.0f / 32.0f) - mu * mu;
                float rs  = rsqrtf(var + LN_EPS);
                float4 o0, o1;
                o0.x = (h[0] - mu) * rs * g0.x + N0.x;
                o0.y = (h[1] - mu) * rs * g0.y + N0.y;
                o0.z = (h[2] - mu) * rs * g0.z + N0.z;
                o0.w = (h[3] - mu) * rs * g0.w + N0.w;
                o1.x = (h[4] - mu) * rs * g1.x + N1.x;
                o1.y = (h[5] - mu) * rs * g1.y + N1.y;
                o1.z = (h[6] - mu) * rs * g1.z + N1.z;
                o1.w = (h[7] - mu) * rs * g1.w + N1.w;
                *reinterpret_cast<float4*>(&itc->xs[nd][ch0])     = o0;
                *reinterpret_cast<float4*>(&itc->xs[nd][ch0 + 4]) = o1;
            }
        }
        __syncthreads();
    }

    // ---- output epilogue: both items ----
    #pragma unroll
    for (int g2 = 0; g2 < 2; g2++) {
        ItemState* itc = (g2 == 0) ? it0 : it1;
        float* outb = out + (size_t)(item0 + g2) * 48 * 32;
        #pragma unroll
        for (int v = t; v < 1536; v += TPB) {
            int o = v >> 5, c = v & 31;
            float val;
            if (o < 16) {               // mean over i; o = j*4+k
                val = itc->xs[o][c] + itc->xs[o + 16][c]
                    + itc->xs[o + 32][c] + itc->xs[o + 48][c];
            } else if (o < 32) {        // mean over j; (o-16) = i*4+k
                int oo = o - 16; int base = (oo >> 2) * 16 + (oo & 3);
                val = itc->xs[base][c] + itc->xs[base + 4][c]
                    + itc->xs[base + 8][c] + itc->xs[base + 12][c];
            } else {                    // mean over k; (o-32) = i*4+j
                int oo = o - 32; int base = (oo >> 2) * 16 + (oo & 3) * 4;
                val = itc->xs[base][c] + itc->xs[base + 1][c]
                    + itc->xs[base + 2][c] + itc->xs[base + 3][c];
            }
            outb[o * 32 + c] = val * 0.25f;
        }
    }
}

extern "C" void kernel_launch(void* const* d_in, const int* in_sizes, int n_in,
                              void* d_out, int out_size) {
    const float* xx        = (const float*)d_in[0];
    const float* ss        = (const float*)d_in[1];
    const float* W_f       = (const float*)d_in[2];
    const float* b_f       = (const float*)d_in[3];
    const float* conv_w    = (const float*)d_in[4];
    const float* conv_root = (const float*)d_in[5];
    const float* conv_bias = (const float*)d_in[6];
    const float* ln_g      = (const float*)d_in[7];
    const float* ln_b      = (const float*)d_in[8];
    // d_in[9]/d_in[10] (src/dst) unused: aggregation has a closed form.

    const int B = in_sizes[1];          // 256 (even)

    cudaFuncSetAttribute(gnn_frame0_kernel,
                         cudaFuncAttributeMaxDynamicSharedMemorySize,
                         (int)sizeof(Smem));
    gnn_frame0_kernel<<<B / 2, TPB, sizeof(Smem)>>>(
        xx, ss, W_f, b_f, conv_w, conv_root, conv_bias, ln_g, ln_b,
        (float*)d_out);
}